// round 4
// baseline (speedup 1.0000x reference)
#include <cuda_runtime.h>
#include <cstdint>

#define B_DIM    8
#define C_OUT    64
#define NK       7
#define GROUP_IN 4
#define C_IN     1792              // 64*4*7
#define L_DIM    4096
#define TILE     512
#define HALO     16                // covers |shift| <= 15, 16B-aligned halo
#define ROWW     (TILE + 2*HALO)   // 544 floats per staged row
#define NCH      (GROUP_IN * NK)   // 28 channels per c_out
#define THREADS  512
#define GRID     152               // one persistent CTA per GB300 SM
#define NTILES   (B_DIM * C_OUT * (L_DIM / TILE))   // 4096 work items
#define BUFSZ    (NCH * ROWW)      // floats per tile buffer

// 16B async copy global->shared; src_size==0 -> zero-fill (implements the
// roll's zero padding: OOB regions are always whole 16B chunks).
__device__ __forceinline__ void cp_async16(uint32_t dst, const void* src, int sz) {
    asm volatile("cp.async.cg.shared.global [%0], [%1], 16, %2;\n"
                 :: "r"(dst), "l"(src), "r"(sz));
}
__device__ __forceinline__ void cp_commit() {
    asm volatile("cp.async.commit_group;\n" ::: "memory");
}
__device__ __forceinline__ void cp_wait1() {
    asm volatile("cp.async.wait_group 1;\n" ::: "memory");
}

// Stage one tile (28 rows x 544 floats, halo'd) into smem buffer at byte
// offset smbuf. Interior chunks are always in-bounds; halo chunks guarded.
__device__ __forceinline__ void stage_tile(int w, uint32_t smbuf,
                                           const float* __restrict__ x, int tid)
{
    const int b   = w >> 9;
    const int rem = w & 511;
    const int co  = rem >> 3;
    const int tx  = rem & 7;
    const int gstart = (tx << 9) - HALO;
    const float* base = x + ((size_t)b * C_IN + (size_t)co * NK) * L_DIM + gstart;

    // interior: 7 passes x 4 rows x 128 chunks, window [t0, t0+512) in-bounds
    {
        const unsigned w2 = (unsigned)tid >> 7;                  // row-in-group 0..3
        const unsigned jj = ((unsigned)tid & 127u) * 4u + HALO;  // float idx [16,524]
        const float* bsrc = base + jj;
        const uint32_t dst0 = smbuf + (w2 * ROWW + jj) * 4u;
        #pragma unroll
        for (int p = 0; p < 7; ++p) {
            unsigned r  = 4u * (unsigned)p + w2;                 // row 0..27
            unsigned rd = r / 7u, rm = r % 7u;
            int crel = (int)(rd * 448u + rm) * L_DIM;
            cp_async16(dst0 + (uint32_t)p * (4u * ROWW * 4u), bsrc + crel, 16);
        }
    }
    // halo: 28 rows x 8 chunks (4 front, 4 back), edge-guarded / zero-filled
    if (tid < NCH * 8) {
        unsigned lc = (unsigned)tid >> 3;
        unsigned h  = (unsigned)tid & 7u;
        unsigned j4 = (h < 4u) ? h * 4u : (TILE + h * 4u);       // 0..12, 528..540
        int gp = gstart + (int)j4;
        unsigned rd = lc / 7u, rm = lc % 7u;
        int crel = (int)(rd * 448u + rm) * L_DIM;
        int sz = (gp >= 0 && gp < L_DIM) ? 16 : 0;
        cp_async16(smbuf + (lc * ROWW + j4) * 4u, base + crel + (int)j4, sz);
    }
}

__global__ __launch_bounds__(THREADS, 1) void addshift_kernel(
    const float* __restrict__ x,
    const int*   __restrict__ si1,
    const int*   __restrict__ si2,
    const int*   __restrict__ si3,
    float*       __restrict__ out)
{
    extern __shared__ float sm[];              // [2][NCH][ROWW]
    __shared__ uint2 tab[C_OUT * NCH];         // per-(co,lc) packed smem byte offsets

    const int tid = threadIdx.x;
    const uint32_t sm_base = (uint32_t)__cvta_generic_to_shared(sm);

    // ---- one-time offset table: offset within row = 16 - shift = 1 + 5*(idx%7),
    // pre-scaled to bytes with row base lc*ROWW*4 folded in (max 58876 < 2^16) ----
    for (int c = tid; c < C_IN; c += THREADS) {
        int g  = c / (C_OUT * NK);
        int r  = c - g * (C_OUT * NK);
        int co = r / NK;
        int k  = r - co * NK;
        int lc = g * NK + k;
        unsigned o1 = 1u + 5u * (unsigned)(si1[c] % NK);
        unsigned o2 = 1u + 5u * (unsigned)(si2[c] % NK);
        unsigned o3 = 1u + 5u * (unsigned)(si3[c] % NK);
        unsigned rb = (unsigned)(lc * ROWW) * 4u;
        tab[co * NCH + lc] = make_uint2((rb + o1 * 4u) | ((rb + o2 * 4u) << 16),
                                         rb + o3 * 4u);
    }
    // (visibility of tab covered by the barrier before the first accumulate)

    const size_t OSZ = (size_t)B_DIM * C_OUT * L_DIM;   // one output tensor

    // ---- pipeline prologue: stage first tile ----
    stage_tile(blockIdx.x, sm_base, x, tid);
    cp_commit();

    int parity = 0;
    for (int w = blockIdx.x; w < NTILES; w += GRID) {
        const int wn = w + GRID;
        if (wn < NTILES)
            stage_tile(wn, sm_base + (uint32_t)((parity ^ 1) * BUFSZ * 4), x, tid);
        cp_commit();               // empty group on final iteration (completes instantly)
        cp_wait1();                // current tile's group fully landed
        __syncthreads();

        // ---- accumulate tile w from buf[parity]: thread owns t = t0 + tid ----
        const int b   = w >> 9;
        const int rem = w & 511;
        const int co  = rem >> 3;
        const int tx  = rem & 7;
        const uint2* tabco = tab + co * NCH;
        const char* smb = (const char*)(sm + parity * BUFSZ) + (size_t)((unsigned)tid * 4u);

        float a1 = 0.f, a2 = 0.f, a3 = 0.f;
        #pragma unroll
        for (int lc = 0; lc < NCH; ++lc) {
            uint2 o = tabco[lc];                      // one LDS.64 broadcast
            a1 += *(const float*)(smb + (o.x & 0xffffu));
            a2 += *(const float*)(smb + (o.x >> 16));
            a3 += *(const float*)(smb + o.y);
        }

        const size_t ob = ((size_t)b * C_OUT + co) * L_DIM + (tx << 9) + tid;
        out[ob]           = a1;
        out[ob + OSZ]     = a2;
        out[ob + 2 * OSZ] = a3;

        __syncthreads();           // buf[parity] free for restaging at w + 2*GRID
        parity ^= 1;
    }
}

extern "C" void kernel_launch(void* const* d_in, const int* in_sizes, int n_in,
                              void* d_out, int out_size) {
    const float* x   = (const float*)d_in[0];
    const int*   si1 = (const int*)d_in[1];
    const int*   si2 = (const int*)d_in[2];
    const int*   si3 = (const int*)d_in[3];
    float* out = (float*)d_out;

    const int smem_bytes = 2 * BUFSZ * (int)sizeof(float);    // 121856
    cudaFuncSetAttribute(addshift_kernel,
                         cudaFuncAttributeMaxDynamicSharedMemorySize, smem_bytes);

    addshift_kernel<<<GRID, THREADS, smem_bytes>>>(x, si1, si2, si3, out);
}

// round 5
// speedup vs baseline: 1.0052x; 1.0052x over previous
#include <cuda_runtime.h>
#include <cstdint>

#define B_DIM    8
#define C_OUT    64
#define NK       7
#define GROUP_IN 4
#define C_IN     1792              // 64*4*7
#define L_DIM    4096
#define TILE     256
#define HALO     16                // covers |shift| <= 15, 16B-aligned halo
#define ROWW     (TILE + 2*HALO)   // 288 floats per staged row
#define NCH      (GROUP_IN * NK)   // 28 channels per c_out
#define THREADS  256
#define GRID     456               // 3 persistent CTAs per GB300 SM
#define NTILES   (B_DIM * C_OUT * (L_DIM / TILE))   // 8192 work items
#define BUFSZ    (NCH * ROWW)      // 8064 floats per tile buffer (32256 B)

// 16B async copy global->shared; src_size==0 -> zero-fill (implements the
// roll's zero padding: OOB regions are always whole 16B chunks).
__device__ __forceinline__ void cp_async16(uint32_t dst, const void* src, int sz) {
    asm volatile("cp.async.cg.shared.global [%0], [%1], 16, %2;\n"
                 :: "r"(dst), "l"(src), "r"(sz));
}
__device__ __forceinline__ void cp_commit() {
    asm volatile("cp.async.commit_group;\n" ::: "memory");
}
__device__ __forceinline__ void cp_wait1() {
    asm volatile("cp.async.wait_group 1;\n" ::: "memory");
}

// Stage one tile (28 rows x 288 floats, halo'd) into smem at byte addr smbuf.
__device__ __forceinline__ void stage_tile(int w, uint32_t smbuf,
                                           const float* __restrict__ x, int tid)
{
    const int b   = w >> 10;
    const int rem = w & 1023;
    const int co  = rem >> 4;
    const int tx  = rem & 15;
    const int gstart = (tx << 8) - HALO;
    const float* base = x + ((size_t)b * C_IN + (size_t)co * NK) * L_DIM + gstart;

    // interior: 7 passes x 4 rows x 64 chunks; window [t0, t0+256) in-bounds
    {
        const unsigned w2 = (unsigned)tid >> 6;                 // row-in-group 0..3
        const unsigned jj = ((unsigned)tid & 63u) * 4u + HALO;  // float idx [16,268]
        const float* bsrc = base + jj;
        const uint32_t dst0 = smbuf + (w2 * ROWW + jj) * 4u;
        #pragma unroll
        for (int p = 0; p < 7; ++p) {
            unsigned r  = 4u * (unsigned)p + w2;                // row 0..27
            unsigned rd = r / 7u, rm = r % 7u;                  // folded at unroll
            int crel = (int)(rd * 448u + rm) * L_DIM;
            cp_async16(dst0 + (uint32_t)p * (4u * ROWW * 4u), bsrc + crel, 16);
        }
    }
    // halo: 28 rows x 8 chunks (4 front, 4 back), edge-guarded / zero-filled
    if (tid < NCH * 8) {
        unsigned lc = (unsigned)tid >> 3;
        unsigned h  = (unsigned)tid & 7u;
        unsigned j4 = (h < 4u) ? h * 4u : (TILE + h * 4u);      // 0..12, 272..284
        int gp = gstart + (int)j4;
        unsigned rd = lc / 7u, rm = lc % 7u;
        int crel = (int)(rd * 448u + rm) * L_DIM;
        int sz = (gp >= 0 && gp < L_DIM) ? 16 : 0;
        cp_async16(smbuf + (lc * ROWW + j4) * 4u, base + crel + (int)j4, sz);
    }
}

__global__ __launch_bounds__(THREADS, 3) void addshift_kernel(
    const float* __restrict__ x,
    const int*   __restrict__ si1,
    const int*   __restrict__ si2,
    const int*   __restrict__ si3,
    float*       __restrict__ out)
{
    extern __shared__ float sm[];              // [2][NCH][ROWW]
    __shared__ unsigned tab[C_OUT * NCH];      // packed per-(co,lc) byte offsets

    const int tid = threadIdx.x;
    const uint32_t sm_base = (uint32_t)__cvta_generic_to_shared(sm);

    // ---- one-time offset table: in-row byte offset = (1 + 5*(idx%7))*4,
    // three 8-bit fields (<=124); row base lc*ROWW*4 folds into LDS immediates ----
    for (int c = tid; c < C_IN; c += THREADS) {
        int g  = c / (C_OUT * NK);
        int r  = c - g * (C_OUT * NK);
        int co = r / NK;
        int k  = r - co * NK;
        int lc = g * NK + k;
        unsigned o1 = 4u + 20u * (unsigned)(si1[c] % NK);
        unsigned o2 = 4u + 20u * (unsigned)(si2[c] % NK);
        unsigned o3 = 4u + 20u * (unsigned)(si3[c] % NK);
        tab[co * NCH + lc] = o1 | (o2 << 8) | (o3 << 16);
    }
    // (tab visibility covered by the barrier before the first accumulate)

    const size_t OSZ = (size_t)B_DIM * C_OUT * L_DIM;   // one output tensor

    // ---- pipeline prologue ----
    stage_tile(blockIdx.x, sm_base, x, tid);
    cp_commit();

    int parity = 0;
    for (int w = blockIdx.x; w < NTILES; w += GRID) {
        const int wn = w + GRID;
        if (wn < NTILES)
            stage_tile(wn, sm_base + (uint32_t)((parity ^ 1) * BUFSZ * 4), x, tid);
        cp_commit();               // empty group on final iteration
        cp_wait1();                // current tile fully landed
        __syncthreads();

        // ---- accumulate tile w from buf[parity]: thread owns t = t0 + tid ----
        const int b   = w >> 10;
        const int rem = w & 1023;
        const int co  = rem >> 4;
        const int tx  = rem & 15;
        const unsigned* tabco = tab + co * NCH;
        const char* smb = (const char*)(sm + parity * BUFSZ)
                        + (size_t)((unsigned)tid * 4u);

        float a1 = 0.f, a2 = 0.f, a3 = 0.f;
        #pragma unroll
        for (int lc = 0; lc < NCH; ++lc) {
            unsigned p = tabco[lc];                 // one LDS.32 broadcast
            a1 += *(const float*)(smb + (p & 255u)         + lc * (ROWW * 4));
            a2 += *(const float*)(smb + ((p >> 8) & 255u)  + lc * (ROWW * 4));
            a3 += *(const float*)(smb + (p >> 16)          + lc * (ROWW * 4));
        }

        const size_t ob = ((size_t)b * C_OUT + co) * L_DIM + (tx << 8) + tid;
        out[ob]           = a1;
        out[ob + OSZ]     = a2;
        out[ob + 2 * OSZ] = a3;

        __syncthreads();           // buf[parity] free for restaging
        parity ^= 1;
    }
}

extern "C" void kernel_launch(void* const* d_in, const int* in_sizes, int n_in,
                              void* d_out, int out_size) {
    const float* x   = (const float*)d_in[0];
    const int*   si1 = (const int*)d_in[1];
    const int*   si2 = (const int*)d_in[2];
    const int*   si3 = (const int*)d_in[3];
    float* out = (float*)d_out;

    const int smem_bytes = 2 * BUFSZ * (int)sizeof(float);    // 64512
    cudaFuncSetAttribute(addshift_kernel,
                         cudaFuncAttributeMaxDynamicSharedMemorySize, smem_bytes);

    addshift_kernel<<<GRID, THREADS, smem_bytes>>>(x, si1, si2, si3, out);
}

// round 6
// speedup vs baseline: 1.0058x; 1.0006x over previous
#include <cuda_runtime.h>
#include <cstdint>

#define B_DIM    8
#define C_OUT    64
#define NK       7
#define GROUP_IN 4
#define C_IN     1792              // 64*4*7
#define L_DIM    4096
#define TILE     256
#define HALO     16                // covers |shift| <= 15, 16B-aligned halo
#define ROWW     (TILE + 2*HALO)   // 288 floats per staged row
#define NCH      (GROUP_IN * NK)   // 28 channels per c_out
#define THREADS  256
#define GRID     456               // 3 persistent CTAs per GB300 SM
#define NTILES   (B_DIM * C_OUT * (L_DIM / TILE))   // 8192 work items
#define BUFSZ    (NCH * ROWW)      // 8064 floats per tile buffer (32256 B)

// 16B async copy global->shared; src_size==0 -> zero-fill (implements the
// roll's zero padding: OOB regions are always whole 16B chunks).
__device__ __forceinline__ void cp_async16(uint32_t dst, const void* src, int sz) {
    asm volatile("cp.async.cg.shared.global [%0], [%1], 16, %2;\n"
                 :: "r"(dst), "l"(src), "r"(sz));
}
__device__ __forceinline__ void cp_commit() {
    asm volatile("cp.async.commit_group;\n" ::: "memory");
}
__device__ __forceinline__ void cp_wait1() {
    asm volatile("cp.async.wait_group 1;\n" ::: "memory");
}

// Stage one tile (28 rows x 288 floats, halo'd) into smem at byte addr smbuf.
__device__ __forceinline__ void stage_tile(int w, uint32_t smbuf,
                                           const float* __restrict__ x, int tid)
{
    const int b   = w >> 10;
    const int rem = w & 1023;
    const int co  = rem >> 4;
    const int tx  = rem & 15;
    const int gstart = (tx << 8) - HALO;
    const float* base = x + ((size_t)b * C_IN + (size_t)co * NK) * L_DIM + gstart;

    // interior: 7 passes x 4 rows x 64 chunks; window [t0, t0+256) in-bounds
    {
        const unsigned w2 = (unsigned)tid >> 6;                 // row-in-group 0..3
        const unsigned jj = ((unsigned)tid & 63u) * 4u + HALO;  // float idx [16,268]
        const float* bsrc = base + jj;
        const uint32_t dst0 = smbuf + (w2 * ROWW + jj) * 4u;
        #pragma unroll
        for (int p = 0; p < 7; ++p) {
            unsigned r  = 4u * (unsigned)p + w2;                // row 0..27
            unsigned rd = r / 7u, rm = r % 7u;                  // folded at unroll
            int crel = (int)(rd * 448u + rm) * L_DIM;
            cp_async16(dst0 + (uint32_t)p * (4u * ROWW * 4u), bsrc + crel, 16);
        }
    }
    // halo: 28 rows x 8 chunks (4 front, 4 back), edge-guarded / zero-filled
    if (tid < NCH * 8) {
        unsigned lc = (unsigned)tid >> 3;
        unsigned h  = (unsigned)tid & 7u;
        unsigned j4 = (h < 4u) ? h * 4u : (TILE + h * 4u);      // 0..12, 272..284
        int gp = gstart + (int)j4;
        unsigned rd = lc / 7u, rm = lc % 7u;
        int crel = (int)(rd * 448u + rm) * L_DIM;
        int sz = (gp >= 0 && gp < L_DIM) ? 16 : 0;
        cp_async16(smbuf + (lc * ROWW + j4) * 4u, base + crel + (int)j4, sz);
    }
}

__global__ __launch_bounds__(THREADS, 3) void addshift_kernel(
    const float* __restrict__ x,
    const int*   __restrict__ si1,
    const int*   __restrict__ si2,
    const int*   __restrict__ si3,
    float*       __restrict__ out)
{
    extern __shared__ float sm[];              // [2][NCH][ROWW]
    __shared__ unsigned tab[C_OUT * NCH];      // packed per-(co,lc) byte offsets

    const int tid = threadIdx.x;
    const uint32_t sm_base = (uint32_t)__cvta_generic_to_shared(sm);

    // ---- one-time offset table: in-row byte offset = (1 + 5*(idx%7))*4,
    // three 8-bit fields (<=124); row base lc*ROWW*4 folds into LDS immediates ----
    for (int c = tid; c < C_IN; c += THREADS) {
        int g  = c / (C_OUT * NK);
        int r  = c - g * (C_OUT * NK);
        int co = r / NK;
        int k  = r - co * NK;
        int lc = g * NK + k;
        unsigned o1 = 4u + 20u * (unsigned)(si1[c] % NK);
        unsigned o2 = 4u + 20u * (unsigned)(si2[c] % NK);
        unsigned o3 = 4u + 20u * (unsigned)(si3[c] % NK);
        tab[co * NCH + lc] = o1 | (o2 << 8) | (o3 << 16);
    }
    // (tab visibility covered by the barrier before the first accumulate)

    const size_t OSZ = (size_t)B_DIM * C_OUT * L_DIM;   // one output tensor

    // ---- pipeline prologue ----
    stage_tile(blockIdx.x, sm_base, x, tid);
    cp_commit();

    int parity = 0;
    for (int w = blockIdx.x; w < NTILES; w += GRID) {
        const int wn = w + GRID;
        if (wn < NTILES)
            stage_tile(wn, sm_base + (uint32_t)((parity ^ 1) * BUFSZ * 4), x, tid);
        cp_commit();               // empty group on final iteration
        cp_wait1();                // current tile fully landed
        __syncthreads();

        // ---- accumulate tile w from buf[parity]: thread owns t = t0 + tid ----
        const int b   = w >> 10;
        const int rem = w & 1023;
        const int co  = rem >> 4;
        const int tx  = rem & 15;
        const unsigned* tabco = tab + co * NCH;
        const char* smb = (const char*)(sm + parity * BUFSZ)
                        + (size_t)((unsigned)tid * 4u);

        float a1 = 0.f, a2 = 0.f, a3 = 0.f;
        #pragma unroll
        for (int lc = 0; lc < NCH; ++lc) {
            unsigned p = tabco[lc];                 // one LDS.32 broadcast
            a1 += *(const float*)(smb + (p & 255u)         + lc * (ROWW * 4));
            a2 += *(const float*)(smb + ((p >> 8) & 255u)  + lc * (ROWW * 4));
            a3 += *(const float*)(smb + (p >> 16)          + lc * (ROWW * 4));
        }

        const size_t ob = ((size_t)b * C_OUT + co) * L_DIM + (tx << 8) + tid;
        out[ob]           = a1;
        out[ob + OSZ]     = a2;
        out[ob + 2 * OSZ] = a3;

        __syncthreads();           // buf[parity] free for restaging
        parity ^= 1;
    }
}

extern "C" void kernel_launch(void* const* d_in, const int* in_sizes, int n_in,
                              void* d_out, int out_size) {
    const float* x   = (const float*)d_in[0];
    const int*   si1 = (const int*)d_in[1];
    const int*   si2 = (const int*)d_in[2];
    const int*   si3 = (const int*)d_in[3];
    float* out = (float*)d_out;

    const int smem_bytes = 2 * BUFSZ * (int)sizeof(float);    // 64512
    cudaFuncSetAttribute(addshift_kernel,
                         cudaFuncAttributeMaxDynamicSharedMemorySize, smem_bytes);

    addshift_kernel<<<GRID, THREADS, smem_bytes>>>(x, si1, si2, si3, out);
}